// round 2
// baseline (speedup 1.0000x reference)
#include <cuda_runtime.h>

#define HH 512
#define WW 512
#define NC 19
#define NB 8
#define OHH 502
#define OWW 502

#define TOX 64
#define TOY 32
#define INX (TOX + 10)   // 74
#define INY (TOY + 10)   // 42
#define NT 256

#define LSE_N (NB * HH * WW)

// smem layout (floats): lse[3108] | p[3108] | h[4*2688=10752] | tgt(780 fl = 3120 B) | red[8]
#define SM_LSE 0
#define SM_P   (INY * INX)
#define SM_H   (2 * INY * INX)
#define SM_TGT (2 * INY * INX + 4 * INY * TOX)
#define SM_RED (SM_TGT + 780)
#define SMEM_SZ ((SM_RED + 8) * 4 + 16)

__device__ float g_lse[LSE_N];
__device__ unsigned char g_tgt[LSE_N];
__device__ float g_acc[NB * NC];
__device__ int g_is64;

__device__ __forceinline__ float ex2f_(float x) { float y; asm("ex2.approx.ftz.f32 %0, %1;" : "=f"(y) : "f"(x)); return y; }
__device__ __forceinline__ float lg2f_(float x) { float y; asm("lg2.approx.f32 %0, %1;" : "=f"(y) : "f"(x)); return y; }

#define L2E 1.4426950408889634f

// ---------------------------------------------------------------------------
// Pass 0: detect whether target buffer is int64 or int32.
// Reads only the first 4KB (always in-bounds). For int64 labels < 2^31 the
// odd 32-bit words are all zero; for random int32 labels they are not.
// ---------------------------------------------------------------------------
__global__ void k_detect(const int* __restrict__ t)
{
    __shared__ int any_nz;
    if (threadIdx.x == 0) any_nz = 0;
    __syncthreads();
    int w = 2 * threadIdx.x + 1;          // odd words 1,3,...,2047
    int nz = 0;
#pragma unroll
    for (int r = 0; r < 4; r++) nz |= t[w + r * 512];
    if (nz) atomicOr(&any_nz, 1);
    __syncthreads();
    if (threadIdx.x == 0) g_is64 = any_nz ? 0 : 1;
}

// ---------------------------------------------------------------------------
// Pass 1: per-pixel softmax log-sum-exp (pre-scaled by log2e) + target->u8
// ---------------------------------------------------------------------------
__global__ __launch_bounds__(NT) void k_softmax(const float* __restrict__ pred,
                                                const void* __restrict__ tgt)
{
    int idx = blockIdx.x * NT + threadIdx.x;
    if (blockIdx.x == 0 && threadIdx.x < NB * NC) g_acc[threadIdx.x] = 0.0f;
    if (idx >= LSE_N) return;
    int b = idx / (HH * WW);
    int hw = idx - b * (HH * WW);
    const float* p = pred + (size_t)b * NC * HH * WW + hw;
    float v[NC];
    float m = -1e30f;
#pragma unroll
    for (int c = 0; c < NC; c++) { v[c] = p[(size_t)c * (HH * WW)]; m = fmaxf(m, v[c]); }
    float s = 0.0f;
#pragma unroll
    for (int c = 0; c < NC; c++) s += ex2f_((v[c] - m) * L2E);
    g_lse[idx] = fmaf(m, L2E, lg2f_(s));   // p_c = ex2(x_c*L2E - L)

    int lab;
    if (g_is64) lab = ((const int*)tgt)[2 * idx];      // low word of LE int64
    else        lab = ((const int*)tgt)[idx];
    g_tgt[idx] = (unsigned char)lab;
}

// ---------------------------------------------------------------------------
// Pass 2: fused softmax-recompute + separable 11x11 Gaussian convs + SSIM
// Fields: 0 = conv(p), 1 = conv(p^2), 2 = conv(p*t), 3 = conv(t) (= conv(t^2))
// ---------------------------------------------------------------------------
__global__ __launch_bounds__(NT) void k_ssim(const float* __restrict__ pred)
{
    extern __shared__ float smem[];
    float* s_lse = smem + SM_LSE;
    float* s_p = smem + SM_P;
    float* s_h = smem + SM_H;
    unsigned char* s_tgt = (unsigned char*)(smem + SM_TGT);
    float* s_red = smem + SM_RED;

    const int tid = threadIdx.x;
    const int b = blockIdx.z;
    const int y0 = blockIdx.y * TOY;
    const int x0 = blockIdx.x * TOX;
    const int warp = tid >> 5, lane = tid & 31;

    // load lse + target tiles once per block
    for (int i = tid; i < INY * INX; i += NT) {
        int r = i / INX, cx = i - r * INX;
        int gy = y0 + r, gx = x0 + cx;
        bool ok = (gy < HH) && (gx < WW);
        int gidx = ok ? ((b * HH + gy) * WW + gx) : 0;
        s_lse[i] = ok ? g_lse[gidx] : 0.0f;
        s_tgt[i] = ok ? g_tgt[gidx] : (unsigned char)255;
    }

    // Gaussian taps (compile-time constants -> FFMA-imm form)
    const float Wt[11] = {0.00102838f, 0.00759876f, 0.03600078f, 0.10936074f,
                          0.21300555f, 0.26601174f, 0.21300555f, 0.10936074f,
                          0.03600078f, 0.00759876f, 0.00102838f};

    for (int c = 0; c < NC; c++) {
        const float* pc = pred + (size_t)(b * NC + c) * (HH * WW);
        __syncthreads();
        // stage p = softmax prob for this class
        for (int i = tid; i < INY * INX; i += NT) {
            int r = i / INX, cx = i - r * INX;
            int gy = y0 + r, gx = x0 + cx;
            bool ok = (gy < HH) && (gx < WW);
            float x = ok ? pc[gy * WW + gx] : 0.0f;
            s_p[i] = ok ? ex2f_(fmaf(x, L2E, -s_lse[i])) : 0.0f;
        }
        __syncthreads();

        // horizontal separable conv: each task = (row, 4 output cols)
        for (int t = tid; t < INY * (TOX / 4); t += NT) {
            int r = t >> 4, u0 = (t & 15) * 4;
            const float* prow = s_p + r * INX + u0;
            const unsigned char* trow = s_tgt + r * INX + u0;
            float pw[14], p2[14], pt[14], iw[14];
#pragma unroll
            for (int k = 0; k < 14; k++) {
                float pv = prow[k];
                bool m = (trow[k] == (unsigned char)c);
                pw[k] = pv;
                p2[k] = pv * pv;
                iw[k] = m ? 1.0f : 0.0f;
                pt[k] = m ? pv : 0.0f;
            }
            int o = r * TOX + u0;
#pragma unroll
            for (int u = 0; u < 4; u++) {
                float hp = 0.f, h2 = 0.f, hq = 0.f, ht = 0.f;
#pragma unroll
                for (int j = 0; j < 11; j++) {
                    hp = fmaf(Wt[j], pw[u + j], hp);
                    h2 = fmaf(Wt[j], p2[u + j], h2);
                    hq = fmaf(Wt[j], pt[u + j], hq);
                    ht = fmaf(Wt[j], iw[u + j], ht);
                }
                s_h[0 * INY * TOX + o + u] = hp;
                s_h[1 * INY * TOX + o + u] = h2;
                s_h[2 * INY * TOX + o + u] = hq;
                s_h[3 * INY * TOX + o + u] = ht;
            }
        }
        __syncthreads();

        // vertical conv (8 outputs/thread sliding window) + SSIM
        float vacc = 0.0f;
        {
            int u = tid & 63, v0 = (tid >> 6) * 8;
            float out[4][8];
#pragma unroll
            for (int f = 0; f < 4; f++) {
                float win[18];
#pragma unroll
                for (int k = 0; k < 18; k++) win[k] = s_h[f * INY * TOX + (v0 + k) * TOX + u];
#pragma unroll
                for (int v = 0; v < 8; v++) {
                    float a = 0.0f;
#pragma unroll
                    for (int j = 0; j < 11; j++) a = fmaf(Wt[j], win[v + j], a);
                    out[f][v] = a;
                }
            }
            int ox = x0 + u;
            if (ox < OWW) {
#pragma unroll
                for (int v = 0; v < 8; v++) {
                    int oy = y0 + v0 + v;
                    if (oy < OHH) {
                        float mu1 = out[0][v], s11 = out[1][v], s12 = out[2][v], mu2 = out[3][v];
                        float mu12 = mu1 * mu2;
                        float m1q = mu1 * mu1, m2q = mu2 * mu2;
                        float var1 = s11 - m1q;
                        float var2 = mu2 - m2q;   // conv(t^2) == conv(t) since t is 0/1
                        float cov = s12 - mu12;
                        float num = (2.0f * mu12 + 1e-4f) * (2.0f * cov + 9e-4f);
                        float den = (m1q + m2q + 1e-4f) * (var1 + var2 + 9e-4f);
                        vacc += __fdividef(num, den);
                    }
                }
            }
        }
#pragma unroll
        for (int off = 16; off > 0; off >>= 1) vacc += __shfl_xor_sync(0xffffffffu, vacc, off);
        if (lane == 0) s_red[warp] = vacc;
        __syncthreads();
        if (tid == 0) {
            float s = 0.0f;
#pragma unroll
            for (int wI = 0; wI < NT / 32; wI++) s += s_red[wI];
            atomicAdd(&g_acc[b * NC + c], s);
        }
    }
}

// ---------------------------------------------------------------------------
// Pass 3: per-(b,c) mean -> relu -> 1 - mean
// ---------------------------------------------------------------------------
__global__ __launch_bounds__(256) void k_final(float* __restrict__ out)
{
    int tid = threadIdx.x;
    __shared__ float sr[8];
    float v = 0.0f;
    if (tid < NB * NC) {
        float a = g_acc[tid] * (1.0f / 252004.0f);   // / (502*502)
        v = a > 0.0f ? a : 0.0f;
    }
#pragma unroll
    for (int off = 16; off > 0; off >>= 1) v += __shfl_xor_sync(0xffffffffu, v, off);
    if ((tid & 31) == 0) sr[tid >> 5] = v;
    __syncthreads();
    if (tid == 0) {
        float s = 0.0f;
#pragma unroll
        for (int i = 0; i < 8; i++) s += sr[i];
        out[0] = 1.0f - s * (1.0f / 152.0f);
    }
}

// ---------------------------------------------------------------------------
extern "C" void kernel_launch(void* const* d_in, const int* in_sizes, int n_in,
                              void* d_out, int out_size)
{
    const float* pred;
    const void* tgt;
    const int PRED_N = NB * NC * HH * WW;
    if (n_in >= 2 && in_sizes[1] == PRED_N) {
        pred = (const float*)d_in[1];
        tgt = d_in[0];
    } else {
        pred = (const float*)d_in[0];
        tgt = (n_in >= 2) ? d_in[1] : d_in[0];
    }

    cudaFuncSetAttribute(k_ssim, cudaFuncAttributeMaxDynamicSharedMemorySize, SMEM_SZ);

    k_detect<<<1, 512>>>((const int*)tgt);
    k_softmax<<<(LSE_N + NT - 1) / NT, NT>>>(pred, tgt);

    dim3 grid((OWW + TOX - 1) / TOX, (OHH + TOY - 1) / TOY, NB);
    k_ssim<<<grid, NT, SMEM_SZ>>>(pred);

    k_final<<<1, 256>>>((float*)d_out);
}

// round 3
// speedup vs baseline: 1.0973x; 1.0973x over previous
#include <cuda_runtime.h>
#include <cuda_fp16.h>

#define HH 512
#define WW 512
#define HW (HH * WW)
#define NC 19
#define NB 8
#define OHH 502
#define OWW 502

#define TOX 64
#define TOY 32
#define INX 74
#define INY 42
#define NT 256
#define HSTR 65                 // row stride of s_h in ULL units (odd -> low bank conflict)

#define LSE_N (NB * HW)
#define NHTASK (INY * 16)       // 672 horizontal tasks

typedef unsigned long long ULL;

// smem byte offsets
#define SMB_H01 0
#define SMB_H23 (INY * HSTR * 8)                  // 21840
#define SMB_P   (2 * INY * HSTR * 8)              // 43680
#define SMB_TGT (SMB_P + INX * INY * 4)           // 56112
#define SMB_RED (SMB_TGT + 3112)                  // 59224
#define SMEM_SZ (SMB_RED + 32)

__device__ __half g_prob[(size_t)NB * NC * HW];   // softmax probs, fp16
__device__ unsigned char g_tgt[LSE_N];
__device__ float g_acc[NB * NC];
__device__ int g_is64;

__device__ __forceinline__ float ex2f_(float x) { float y; asm("ex2.approx.ftz.f32 %0, %1;" : "=f"(y) : "f"(x)); return y; }
__device__ __forceinline__ float lg2f_(float x) { float y; asm("lg2.approx.f32 %0, %1;" : "=f"(y) : "f"(x)); return y; }
__device__ __forceinline__ ULL pk2(float lo, float hi) { ULL r; asm("mov.b64 %0, {%1, %2};" : "=l"(r) : "f"(lo), "f"(hi)); return r; }
__device__ __forceinline__ void upk2(float& lo, float& hi, ULL v) { asm("mov.b64 {%0, %1}, %2;" : "=f"(lo), "=f"(hi) : "l"(v)); }
__device__ __forceinline__ ULL fma2(ULL a, ULL b, ULL c) { ULL d; asm("fma.rn.f32x2 %0, %1, %2, %3;" : "=l"(d) : "l"(a), "l"(b), "l"(c)); return d; }

#define L2E 1.4426950408889634f

// ---------------------------------------------------------------------------
// Pass 0: detect int64 vs int32 target (reads only first 4KB, always in-bounds)
// ---------------------------------------------------------------------------
__global__ void k_detect(const int* __restrict__ t)
{
    __shared__ int any_nz;
    if (threadIdx.x == 0) any_nz = 0;
    __syncthreads();
    int w = 2 * threadIdx.x + 1;
    int nz = 0;
#pragma unroll
    for (int r = 0; r < 4; r++) nz |= t[w + r * 512];
    if (nz) atomicOr(&any_nz, 1);
    __syncthreads();
    if (threadIdx.x == 0) g_is64 = any_nz ? 0 : 1;
}

// ---------------------------------------------------------------------------
// Pass 1: per-pixel softmax -> fp16 probs, target -> u8
// ---------------------------------------------------------------------------
__global__ __launch_bounds__(NT) void k_softmax(const float* __restrict__ pred,
                                                const void* __restrict__ tgt)
{
    int idx = blockIdx.x * NT + threadIdx.x;
    if (blockIdx.x == 0 && threadIdx.x < NB * NC) g_acc[threadIdx.x] = 0.0f;
    if (idx >= LSE_N) return;
    int b = idx / HW;
    int hw = idx - b * HW;
    const float* p = pred + (size_t)b * NC * HW + hw;
    float v[NC];
    float m = -1e30f;
#pragma unroll
    for (int c = 0; c < NC; c++) { v[c] = p[(size_t)c * HW]; m = fmaxf(m, v[c]); }
    float s = 0.0f;
#pragma unroll
    for (int c = 0; c < NC; c++) s += ex2f_((v[c] - m) * L2E);
    float L = fmaf(m, L2E, lg2f_(s));
    __half* q = g_prob + (size_t)b * NC * HW + hw;
#pragma unroll
    for (int c = 0; c < NC; c++)
        q[(size_t)c * HW] = __float2half(ex2f_(fmaf(v[c], L2E, -L)));

    int lab;
    if (g_is64) lab = ((const int*)tgt)[2 * idx];   // low word of LE int64
    else        lab = ((const int*)tgt)[idx];
    g_tgt[idx] = (unsigned char)lab;
}

// ---------------------------------------------------------------------------
// Pass 2: separable 11x11 Gaussian convs (f32x2-packed, 2 field-pairs) + SSIM
// pair01 = (p, p^2) -> (mu1, conv(p^2));  pair23 = (p*t, t) -> (conv(pt), mu2)
// ---------------------------------------------------------------------------
__global__ __launch_bounds__(NT) void k_ssim()
{
    extern __shared__ char smem[];
    ULL* s_h01 = (ULL*)(smem + SMB_H01);
    ULL* s_h23 = (ULL*)(smem + SMB_H23);
    float* s_p = (float*)(smem + SMB_P);
    unsigned char* s_tgt = (unsigned char*)(smem + SMB_TGT);
    float* s_red = (float*)(smem + SMB_RED);

    const int tid = threadIdx.x;
    const int b = blockIdx.z;
    const int y0 = blockIdx.y * TOY;
    const int x0 = blockIdx.x * TOX;
    const int warp = tid >> 5, lane = tid & 31;

    // stage target tile once
    for (int i = tid; i < INY * INX; i += NT) {
        int r = i / INX, cx = i - r * INX;
        int gy = y0 + r, gx = x0 + cx;
        bool ok = (gy < HH) && (gx < WW);
        int gidx = ok ? ((b * HH + gy) * WW + gx) : 0;
        s_tgt[i] = ok ? g_tgt[gidx] : (unsigned char)255;
    }

    const float Wt[11] = {0.00102838f, 0.00759876f, 0.03600078f, 0.10936074f,
                          0.21300555f, 0.26601174f, 0.21300555f, 0.10936074f,
                          0.03600078f, 0.00759876f, 0.00102838f};
    ULL ww[11];
#pragma unroll
    for (int j = 0; j < 11; j++) ww[j] = pk2(Wt[j], Wt[j]);

    for (int c = 0; c < NC; c++) {
        const __half* plane = g_prob + (size_t)(b * NC + c) * HW;
        __syncthreads();
        // stage fp16 probs -> fp32 smem
        for (int i = tid; i < INY * INX; i += NT) {
            int r = i / INX, cx = i - r * INX;
            int gy = y0 + r, gx = x0 + cx;
            bool ok = (gy < HH) && (gx < WW);
            s_p[i] = ok ? __half2float(plane[gy * WW + gx]) : 0.0f;
        }
        __syncthreads();

        // horizontal conv: task = (row r, 4 output cols). lanes span rows.
        for (int t = tid; t < NHTASK; t += NT) {
            int q = t / INY;
            int r = t - q * INY;
            int u0 = q * 4;
            const float* prow = s_p + r * INX + u0;
            const unsigned char* trow = s_tgt + r * INX + u0;
            ULL w01[14], w23[14];
#pragma unroll
            for (int k = 0; k < 14; k++) {
                float pv = prow[k];
                bool m = (trow[k] == (unsigned char)c);
                w01[k] = pk2(pv, pv * pv);
                w23[k] = pk2(m ? pv : 0.0f, m ? 1.0f : 0.0f);
            }
            ULL* o01 = s_h01 + r * HSTR + u0;
            ULL* o23 = s_h23 + r * HSTR + u0;
#pragma unroll
            for (int u = 0; u < 4; u++) {
                ULL a01 = 0ull, a23 = 0ull;
#pragma unroll
                for (int j = 0; j < 11; j++) {
                    a01 = fma2(ww[j], w01[u + j], a01);
                    a23 = fma2(ww[j], w23[u + j], a23);
                }
                o01[u] = a01;
                o23[u] = a23;
            }
        }
        __syncthreads();

        // vertical conv (packed) + SSIM
        float vacc = 0.0f;
        {
            const int u = tid & 63;
            const int v0 = (tid >> 6) * 8;
            float mu1v[8], s11v[8], s12v[8], mu2v[8];
            {
                ULL win[18];
#pragma unroll
                for (int k = 0; k < 18; k++) win[k] = s_h01[(v0 + k) * HSTR + u];
#pragma unroll
                for (int v = 0; v < 8; v++) {
                    ULL a = 0ull;
#pragma unroll
                    for (int j = 0; j < 11; j++) a = fma2(ww[j], win[v + j], a);
                    upk2(mu1v[v], s11v[v], a);
                }
            }
            {
                ULL win[18];
#pragma unroll
                for (int k = 0; k < 18; k++) win[k] = s_h23[(v0 + k) * HSTR + u];
#pragma unroll
                for (int v = 0; v < 8; v++) {
                    ULL a = 0ull;
#pragma unroll
                    for (int j = 0; j < 11; j++) a = fma2(ww[j], win[v + j], a);
                    upk2(s12v[v], mu2v[v], a);
                }
            }
            int ox = x0 + u;
            if (ox < OWW) {
#pragma unroll
                for (int v = 0; v < 8; v++) {
                    int oy = y0 + v0 + v;
                    if (oy < OHH) {
                        float mu1 = mu1v[v], s11 = s11v[v], s12 = s12v[v], mu2 = mu2v[v];
                        float mu12 = mu1 * mu2;
                        float m1q = mu1 * mu1, m2q = mu2 * mu2;
                        float var1 = s11 - m1q;
                        float var2 = mu2 - m2q;      // conv(t^2) == conv(t)
                        float cov = s12 - mu12;
                        float num = (2.0f * mu12 + 1e-4f) * (2.0f * cov + 9e-4f);
                        float den = (m1q + m2q + 1e-4f) * (var1 + var2 + 9e-4f);
                        vacc += __fdividef(num, den);
                    }
                }
            }
        }
#pragma unroll
        for (int off = 16; off > 0; off >>= 1) vacc += __shfl_xor_sync(0xffffffffu, vacc, off);
        if (lane == 0) s_red[warp] = vacc;
        __syncthreads();
        if (tid == 0) {
            float s = 0.0f;
#pragma unroll
            for (int wI = 0; wI < NT / 32; wI++) s += s_red[wI];
            atomicAdd(&g_acc[b * NC + c], s);
        }
    }
}

// ---------------------------------------------------------------------------
// Pass 3: per-(b,c) mean -> relu -> 1 - mean
// ---------------------------------------------------------------------------
__global__ __launch_bounds__(256) void k_final(float* __restrict__ out)
{
    int tid = threadIdx.x;
    __shared__ float sr[8];
    float v = 0.0f;
    if (tid < NB * NC) {
        float a = g_acc[tid] * (1.0f / 252004.0f);
        v = a > 0.0f ? a : 0.0f;
    }
#pragma unroll
    for (int off = 16; off > 0; off >>= 1) v += __shfl_xor_sync(0xffffffffu, v, off);
    if ((tid & 31) == 0) sr[tid >> 5] = v;
    __syncthreads();
    if (tid == 0) {
        float s = 0.0f;
#pragma unroll
        for (int i = 0; i < 8; i++) s += sr[i];
        out[0] = 1.0f - s * (1.0f / 152.0f);
    }
}

// ---------------------------------------------------------------------------
extern "C" void kernel_launch(void* const* d_in, const int* in_sizes, int n_in,
                              void* d_out, int out_size)
{
    const float* pred;
    const void* tgt;
    const int PRED_N = NB * NC * HH * WW;
    if (n_in >= 2 && in_sizes[1] == PRED_N) {
        pred = (const float*)d_in[1];
        tgt = d_in[0];
    } else {
        pred = (const float*)d_in[0];
        tgt = (n_in >= 2) ? d_in[1] : d_in[0];
    }

    cudaFuncSetAttribute(k_ssim, cudaFuncAttributeMaxDynamicSharedMemorySize, SMEM_SZ);

    k_detect<<<1, 512>>>((const int*)tgt);
    k_softmax<<<(LSE_N + NT - 1) / NT, NT>>>(pred, tgt);

    dim3 grid((OWW + TOX - 1) / TOX, (OHH + TOY - 1) / TOY, NB);
    k_ssim<<<grid, NT, SMEM_SZ>>>();

    k_final<<<1, 256>>>((float*)d_out);
}